// round 13
// baseline (speedup 1.0000x reference)
#include <cuda_runtime.h>
#include <cuda_bf16.h>
#include <cstdint>
#include <math.h>

#define NQ     65536
#define DIMIN  1024
#define DIMH   256
#define NCLUS  8
#define BM     128
#define BN     256
#define BK     64
#define NTILE  (NQ / BM)       // 512 tiles
#define FULLT  444             // 148*3 full tiles
#define NSPLIT (NTILE - FULLT) // 68 split tiles
#define NGRID  (FULLT + 2 * NSPLIT)  // 580
#define NITER  (DIMIN / BK)    // 16
#define WCONV  148             // wave-1 blocks do W1 convert + zeroing
#define TAILN  64
#define TICK0  (NGRID - TAILN) // 516
#define SEG_SCALE 4294967296.0

// smem layout (bytes)
#define LDA      144
#define STAGE_A  (128 * LDA)
#define STAGE_B  (256 * LDA)
#define STAGE    (STAGE_A + STAGE_B)
#define OFF_A(s) ((unsigned)(s) * STAGE)
#define OFF_B(s) ((unsigned)(s) * STAGE + STAGE_A)
#define HLD      260
#define OFF_EXTRA 133120u
#define OFF_B1   OFF_EXTRA
#define OFF_CID  (OFF_B1 + 1024u)
#define OFF_CNT  (OFF_CID + 512u)
#define OFF_FLG  (OFF_CNT + 32u)
#define SMEM_DYN (OFF_FLG + 16u)

// ---- device scratch ----
__device__ __nv_bfloat16 g_W1bf[DIMH * DIMIN];          // 512 KB
__device__ float g_comb[NSPLIT * 2 * 32768];            // split-K halves
__device__ unsigned g_tick[NSPLIT];
__device__ unsigned long long g_segi[NCLUS * DIMH];
__device__ unsigned g_cnti[NCLUS];
__device__ float g_hp[NCLUS * DIMH];
__device__ float g_part[NCLUS * 8];
__device__ unsigned g_w1flag;
__device__ unsigned g_done1, g_done2, g_done3;

// ---- helpers ----
__device__ __forceinline__ uint32_t smem_u32(const void* p) {
    uint32_t a;
    asm("{ .reg .u64 t; cvta.to.shared.u64 t, %1; cvt.u32.u64 %0, t; }" : "=r"(a) : "l"(p));
    return a;
}

__device__ __forceinline__ void ldm4(uint32_t* r, uint32_t addr) {
    asm volatile("ldmatrix.sync.aligned.m8n8.x4.shared.b16 {%0,%1,%2,%3}, [%4];"
                 : "=r"(r[0]), "=r"(r[1]), "=r"(r[2]), "=r"(r[3]) : "r"(addr));
}

__device__ __forceinline__ void mma_bf16(float* d, const uint32_t* a,
                                         uint32_t b0, uint32_t b1) {
    asm volatile("mma.sync.aligned.m16n8k16.row.col.f32.bf16.bf16.f32 "
                 "{%0,%1,%2,%3}, {%4,%5,%6,%7}, {%8,%9}, {%0,%1,%2,%3};"
                 : "+f"(d[0]), "+f"(d[1]), "+f"(d[2]), "+f"(d[3])
                 : "r"(a[0]), "r"(a[1]), "r"(a[2]), "r"(a[3]), "r"(b0), "r"(b1));
}

__device__ __forceinline__ void cp_B(uint32_t base, int s, int k0, int tid) {
    uint32_t dst = base + OFF_B(s);
    const char* src = (const char*)g_W1bf + (size_t)k0 * 2;
    #pragma unroll
    for (int i = 0; i < 8; i++) {
        int c  = tid + 256 * i;
        int n  = c >> 3, kc = c & 7;
        uint32_t d = dst + (unsigned)n * LDA + (unsigned)kc * 16;
        const void* g = src + (size_t)n * (DIMIN * 2) + kc * 16;
        asm volatile("cp.async.cg.shared.global [%0], [%1], 16;" :: "r"(d), "l"(g));
    }
}

__device__ __forceinline__ void ldgA(float4* areg, const float* x,
                                     int row0, int it, int tid, int h) {
    const int r0 = h * 64 + (tid >> 4), fc = tid & 15;
    const float* p = x + (size_t)(row0 + r0) * DIMIN + it * BK + fc * 4;
    #pragma unroll
    for (int i = 0; i < 4; i++)
        areg[i] = *(const float4*)(p + (size_t)(16 * i) * DIMIN);
}

__device__ __forceinline__ void stsA(uint32_t sA, const float4* areg, int tid, int h) {
    const int r0 = h * 64 + (tid >> 4), fc = tid & 15;
    #pragma unroll
    for (int i = 0; i < 4; i++) {
        __nv_bfloat162 lo = __floats2bfloat162_rn(areg[i].x, areg[i].y);
        __nv_bfloat162 hi = __floats2bfloat162_rn(areg[i].z, areg[i].w);
        uint32_t u0 = *(uint32_t*)&lo, u1 = *(uint32_t*)&hi;
        uint32_t d = sA + (unsigned)(r0 + 16 * i) * LDA + (unsigned)fc * 8;
        asm volatile("st.shared.v2.b32 [%0], {%1,%2};" :: "r"(d), "r"(u0), "r"(u1));
    }
}

// ---------------------------------------------------------------------------
// Megakernel: W1 convert (wave-1) -> GEMM+segsum -> fused tail (last 64)
// ---------------------------------------------------------------------------
__global__ __launch_bounds__(256, 1)
void k_mega(const float* __restrict__ x, const int* __restrict__ cid,
            const float* __restrict__ W1, const float* __restrict__ b1,
            const float* __restrict__ Wf, const float* __restrict__ bfv,
            const float* __restrict__ Wa, const float* __restrict__ ba,
            const float* __restrict__ Wb, const float* __restrict__ bb,
            const float* __restrict__ Wc, const float* __restrict__ bc,
            float* __restrict__ out)
{
    extern __shared__ char sm[];
    const uint32_t base = smem_u32(sm);
    float* b1s   = (float*)(sm + OFF_B1);
    int*   cid_s = (int*)  (sm + OFF_CID);
    int*   cnt_s = (int*)  (sm + OFF_CNT);
    int*   flg_s = (int*)  (sm + OFF_FLG);

    const int tid  = threadIdx.x;
    const int lane = tid & 31, warp = tid >> 5;
    const int wn = warp & 3, wm = warp >> 2;

    // ---- Phase 0: wave-1 blocks convert W1 fp32->bf16 + zero run-state ----
    if (blockIdx.x < WCONV) {
        for (int j = blockIdx.x * 256 + tid; j < DIMH * DIMIN / 4; j += WCONV * 256) {
            float4 v = ((const float4*)W1)[j];
            __nv_bfloat162 lo = __floats2bfloat162_rn(v.x, v.y);
            __nv_bfloat162 hi = __floats2bfloat162_rn(v.z, v.w);
            uint2 u;
            u.x = *(uint32_t*)&lo;
            u.y = *(uint32_t*)&hi;
            *(uint2*)&g_W1bf[j * 4] = u;
        }
        int j2 = blockIdx.x * 256 + tid;
        if (j2 < NCLUS * DIMH) g_segi[j2] = 0ull;
        if (j2 < NCLUS)        g_cnti[j2] = 0u;
        __threadfence();
        __syncthreads();
        if (tid == 0) atomicAdd(&g_w1flag, 1u);
    }
    if (tid == 0) {
        while (atomicAdd(&g_w1flag, 0u) < (unsigned)WCONV) __nanosleep(32);
    }
    __syncthreads();

    // ---- tile mapping (R12 split-K layout) ----
    int tile, it0, itN, halfidx = 0;
    const bool split = (blockIdx.x >= FULLT);
    if (!split) { tile = blockIdx.x; it0 = 0; itN = NITER; }
    else {
        int j = blockIdx.x - FULLT;
        tile = FULLT + (j >> 1);
        halfidx = j & 1;
        it0 = halfidx * (NITER / 2);
        itN = it0 + NITER / 2;
    }
    const int row0 = tile * BM;

    if (tid < 8)   cnt_s[tid] = 0;
    b1s[tid] = b1[tid];
    if (tid < 128) cid_s[tid] = cid[row0 + tid];

    float acc[4][8][4];
    #pragma unroll
    for (int mt = 0; mt < 4; mt++)
        #pragma unroll
        for (int nt = 0; nt < 8; nt++)
            #pragma unroll
            for (int q = 0; q < 4; q++) acc[mt][nt][q] = 0.0f;

    float4 areg[4];
    cp_B(base, 0, it0 * BK, tid);
    asm volatile("cp.async.commit_group;" ::: "memory");
    ldgA(areg, x, row0, it0, tid, 0);
    stsA(base + OFF_A(0), areg, tid, 0);
    ldgA(areg, x, row0, it0, tid, 1);
    stsA(base + OFF_A(0), areg, tid, 1);
    asm volatile("cp.async.wait_group 0;" ::: "memory");
    __syncthreads();

    for (int it = it0; it < itN; it++) {
        const int s = (it - it0) & 1;
        const bool nxt = (it + 1 < itN);
        if (nxt) {
            cp_B(base, s ^ 1, (it + 1) * BK, tid);
            asm volatile("cp.async.commit_group;" ::: "memory");
            ldgA(areg, x, row0, it + 1, tid, 0);
        }
        const uint32_t sA = base + OFF_A(s), sB = base + OFF_B(s);

        #pragma unroll
        for (int half = 0; half < 2; half++) {
            #pragma unroll
            for (int kq = 0; kq < 2; kq++) {
                const int ks = half * 2 + kq;
                uint32_t a[4][4];
                const uint32_t abase = sA + (unsigned)(wm * 64 + (lane & 15)) * LDA
                                     + (unsigned)ks * 32 + (unsigned)(lane >> 4) * 16;
                #pragma unroll
                for (int mt = 0; mt < 4; mt++)
                    ldm4(a[mt], abase + (unsigned)(mt * 16) * LDA);
                #pragma unroll
                for (int j = 0; j < 4; j++) {
                    uint32_t b[4];
                    ldm4(b, sB + (unsigned)(wn * 64 + j * 16 + (lane & 15)) * LDA
                              + (unsigned)ks * 32 + (unsigned)(lane >> 4) * 16);
                    #pragma unroll
                    for (int mt = 0; mt < 4; mt++) {
                        mma_bf16(acc[mt][2 * j],     a[mt], b[0], b[2]);
                        mma_bf16(acc[mt][2 * j + 1], a[mt], b[1], b[3]);
                    }
                }
            }
            if (nxt) {
                stsA(base + OFF_A(s ^ 1), areg, tid, half);
                if (half == 0) ldgA(areg, x, row0, it + 1, tid, 1);
                else asm volatile("cp.async.wait_group 0;" ::: "memory");
            }
        }
        __syncthreads();
    }

    // ---- split-K combine ----
    bool do_epi = true;
    if (split) {
        const int ts = tile - FULLT;
        float* myb = g_comb + (size_t)ts * 65536 + (size_t)halfidx * 32768;
        #pragma unroll
        for (int mt = 0; mt < 4; mt++)
            #pragma unroll
            for (int nt = 0; nt < 8; nt++)
                #pragma unroll
                for (int q = 0; q < 4; q++) {
                    int qi = (mt * 8 + nt) * 4 + q;
                    myb[qi * 256 + tid] = acc[mt][nt][q];
                }
        __threadfence();
        __syncthreads();
        if (tid == 0) flg_s[0] = (int)atomicAdd(&g_tick[ts], 1u);
        __syncthreads();
        if (flg_s[0] == 0) do_epi = false;
        else {
            __threadfence();
            const float* ob = g_comb + (size_t)ts * 65536 + (size_t)(1 - halfidx) * 32768;
            #pragma unroll
            for (int mt = 0; mt < 4; mt++)
                #pragma unroll
                for (int nt = 0; nt < 8; nt++)
                    #pragma unroll
                    for (int q = 0; q < 4; q++) {
                        int qi = (mt * 8 + nt) * 4 + q;
                        acc[mt][nt][q] += ob[qi * 256 + tid];
                    }
        }
    }

    // ---- epilogue: bias+relu+cluster sums -> deterministic atomics ----
    if (do_epi) {
        float* hbuf = (float*)sm;
        #pragma unroll
        for (int mt = 0; mt < 4; mt++)
            #pragma unroll
            for (int nt = 0; nt < 8; nt++) {
                int gm = wm * 64 + mt * 16 + (lane >> 2);
                int gn = wn * 64 + nt * 8 + 2 * (lane & 3);
                hbuf[gm * HLD + gn]           = acc[mt][nt][0];
                hbuf[gm * HLD + gn + 1]       = acc[mt][nt][1];
                hbuf[(gm + 8) * HLD + gn]     = acc[mt][nt][2];
                hbuf[(gm + 8) * HLD + gn + 1] = acc[mt][nt][3];
            }

        if (tid < 128) {
            int cidv = cid_s[tid];
            #pragma unroll
            for (int c = 0; c < 8; c++) {
                unsigned m = __ballot_sync(0xffffffffu, cidv == c);
                if (lane == c) atomicAdd(&cnt_s[c], __popc(m));
            }
        }
        __syncthreads();

        const float bt = b1s[tid];
        float sacc[NCLUS];
        #pragma unroll
        for (int c = 0; c < NCLUS; c++) sacc[c] = 0.0f;
        #pragma unroll 4
        for (int r = 0; r < 128; r++) {
            float v = fmaxf(hbuf[r * HLD + tid] + bt, 0.0f);
            int cd = cid_s[r];
            #pragma unroll
            for (int c = 0; c < NCLUS; c++) sacc[c] += (cd == c) ? v : 0.0f;
        }
        #pragma unroll
        for (int c = 0; c < NCLUS; c++) {
            unsigned long long q = (unsigned long long)llrint((double)sacc[c] * SEG_SCALE);
            atomicAdd(&g_segi[c * DIMH + tid], q);
        }
        if (tid < 8) atomicAdd(&g_cnti[tid], (unsigned)cnt_s[tid]);
    }

    // ---- finish ticket ----
    __threadfence();
    __syncthreads();
    if (tid == 0) flg_s[1] = (int)atomicAdd(&g_done1, 1u);
    __syncthreads();
    const int t = flg_s[1];
    if (t < TICK0) return;

    // last 64 CTAs: wait for all epilogues
    if (tid == 0) { while (atomicAdd(&g_done1, 0u) < (unsigned)NGRID) __nanosleep(32); }
    __syncthreads();
    __threadfence();

    const int u = t - TICK0, c = u >> 3, og = u & 7;   // cluster, 32-row group
    float* hc_s = (float*)sm;
    float* hp_s = (float*)(sm + 1024);
    float* rr   = (float*)(sm + 2048);
    float* prt  = (float*)(sm + 2304);
    float* lg   = (float*)(sm + 2816);

    // Phase 1: hp = relu(Wf hc + bf)
    {
        float inv = 1.0f / fmaxf((float)g_cnti[c], 1.0f);
        hc_s[tid] = (float)((double)g_segi[c * DIMH + tid] * (1.0 / SEG_SCALE)) * inv;
        __syncthreads();

        const int row = og * 32 + (tid >> 3);
        const int k0  = (tid & 7) * 32;
        const float4* w = (const float4*)(Wf + (size_t)row * DIMH + k0);
        float a = 0.0f;
        #pragma unroll
        for (int k = 0; k < 8; k++) {
            float4 wv = w[k];
            a += wv.x * hc_s[k0 + 4 * k]     + wv.y * hc_s[k0 + 4 * k + 1]
               + wv.z * hc_s[k0 + 4 * k + 2] + wv.w * hc_s[k0 + 4 * k + 3];
        }
        #pragma unroll
        for (int o = 4; o > 0; o >>= 1)
            a += __shfl_xor_sync(0xffffffffu, a, o);
        if ((tid & 7) == 0)
            g_hp[c * DIMH + row] = fmaxf(a + bfv[row], 0.0f);
    }
    __threadfence();
    __syncthreads();
    if (tid == 0) {
        atomicAdd(&g_done2, 1u);
        while (atomicAdd(&g_done2, 0u) < (unsigned)TAILN) __nanosleep(32);
    }
    __syncthreads();
    __threadfence();

    // Phase 2: gated logit partials
    {
        hp_s[tid] = g_hp[c * DIMH + tid];
        __syncthreads();

        const int row = og * 32 + (tid >> 3);
        const int k0  = (tid & 7) * 32;
        const float4* wa = (const float4*)(Wa + (size_t)row * DIMH + k0);
        const float4* wb = (const float4*)(Wb + (size_t)row * DIMH + k0);
        float aa = 0.0f, gg = 0.0f;
        #pragma unroll
        for (int k = 0; k < 8; k++) {
            float4 av = wa[k], bv = wb[k];
            float h0 = hp_s[k0 + 4 * k], h1 = hp_s[k0 + 4 * k + 1];
            float h2 = hp_s[k0 + 4 * k + 2], h3 = hp_s[k0 + 4 * k + 3];
            aa += av.x * h0 + av.y * h1 + av.z * h2 + av.w * h3;
            gg += bv.x * h0 + bv.y * h1 + bv.z * h2 + bv.w * h3;
        }
        #pragma unroll
        for (int o = 4; o > 0; o >>= 1) {
            aa += __shfl_xor_sync(0xffffffffu, aa, o);
            gg += __shfl_xor_sync(0xffffffffu, gg, o);
        }
        if ((tid & 7) == 0) {
            float a2 = aa + ba[row], g2 = gg + bb[row];
            rr[tid >> 3] = tanhf(a2) * (1.0f / (1.0f + expf(-g2))) * Wc[row];
        }
        __syncthreads();
        if (tid == 0) {
            float s = 0.0f;
            #pragma unroll
            for (int r = 0; r < 32; r++) s += rr[r];
            g_part[c * 8 + og] = s;
            __threadfence();
            flg_s[2] = (int)atomicAdd(&g_done3, 1u);
        }
        __syncthreads();
    }
    if (flg_s[2] != TAILN - 1) return;

    // ---- final block: softmax + weighted sum + state reset ----
    __threadfence();
    if (tid < 64) prt[tid] = g_part[tid];
    __syncthreads();
    if (tid < 8) {
        float s = bc[0];
        #pragma unroll
        for (int k = 0; k < 8; k++) s += prt[tid * 8 + k];
        lg[tid] = s;
    }
    __syncthreads();
    float l[NCLUS], m = -1e30f;
    #pragma unroll
    for (int cc = 0; cc < NCLUS; cc++) { l[cc] = lg[cc]; m = fmaxf(m, l[cc]); }
    float S = 0.0f;
    #pragma unroll
    for (int cc = 0; cc < NCLUS; cc++) { l[cc] = expf(l[cc] - m); S += l[cc]; }
    float o = 0.0f;
    #pragma unroll
    for (int cc = 0; cc < NCLUS; cc++) o += l[cc] * g_hp[cc * DIMH + tid];
    out[tid] = o / S;

    // replay-safe reset (no other CTA alive)
    if (tid == 0) { g_done1 = 0; g_done2 = 0; g_done3 = 0; g_w1flag = 0; }
    if (tid < NSPLIT) g_tick[tid] = 0u;
    __threadfence();
}

// ---------------------------------------------------------------------------
extern "C" void kernel_launch(void* const* d_in, const int* in_sizes, int n_in,
                              void* d_out, int out_size)
{
    const float* x   = (const float*)d_in[0];
    const int*   cid = (const int*)  d_in[1];
    const float* W1  = (const float*)d_in[2];
    const float* b1  = (const float*)d_in[3];
    const float* Wf  = (const float*)d_in[4];
    const float* bf  = (const float*)d_in[5];
    const float* Wa  = (const float*)d_in[6];
    const float* ba  = (const float*)d_in[7];
    const float* Wb  = (const float*)d_in[8];
    const float* bb  = (const float*)d_in[9];
    const float* Wc  = (const float*)d_in[10];
    const float* bc  = (const float*)d_in[11];

    cudaFuncSetAttribute(k_mega, cudaFuncAttributeMaxDynamicSharedMemorySize, SMEM_DYN);

    k_mega<<<NGRID, 256, SMEM_DYN>>>(x, cid, W1, b1, Wf, bf, Wa, ba, Wb, bb, Wc, bc,
                                     (float*)d_out);
}